// round 6
// baseline (speedup 1.0000x reference)
#include <cuda_runtime.h>
#include <cstdint>

#define BATCH 4
#define HEADS 16
#define SEQ   2048
#define DH    64
#define BM    64        // query rows per CTA (2 lanes per row: D split in halves)
#define BN    32        // key/value tile
#define NT    128
#define NTILES (SEQ / BN)
#define MST   65        // padded stride of mask/score buffer [BN][MST]

typedef unsigned long long ull;

// ---- packed f32x2 helpers (sm_100+) --------------------------------------
__device__ __forceinline__ ull pack2(float lo, float hi) {
    ull r; asm("mov.b64 %0,{%1,%2};" : "=l"(r) : "f"(lo), "f"(hi)); return r;
}
__device__ __forceinline__ void unpack2(ull v, float& lo, float& hi) {
    asm("mov.b64 {%0,%1},%2;" : "=f"(lo), "=f"(hi) : "l"(v));
}
__device__ __forceinline__ ull fma2(ull a, ull b, ull c) {
    ull d; asm("fma.rn.f32x2 %0,%1,%2,%3;" : "=l"(d) : "l"(a), "l"(b), "l"(c)); return d;
}
__device__ __forceinline__ ull mul2(ull a, ull b) {
    ull d; asm("mul.rn.f32x2 %0,%1,%2;" : "=l"(d) : "l"(a), "l"(b)); return d;
}
__device__ __forceinline__ ull add2(ull a, ull b) {
    ull d; asm("add.rn.f32x2 %0,%1,%2;" : "=l"(d) : "l"(a), "l"(b)); return d;
}

// ---- fast exp on the fma/alu pipes (no MUFU) -----------------------------
// exp(x) for x <= 0. Magic-constant round, degree-5 Taylor for 2^f, exponent
// spliced via integer add ( bits(12582912+k)<<23 == k<<23 exactly ).
// Rel error ~3e-6. Clamp makes x = -1e30 (masked sentinel) yield ~2e-38 ~ 0.
__device__ __forceinline__ float fexp(float x) {
    float t = x * 1.4426950408889634f;
    t = fmaxf(t, -125.0f);
    float z  = t + 12582912.0f;          // round-to-nearest int in low bits
    float kf = z - 12582912.0f;
    float f  = t - kf;                   // f in [-0.5, 0.5]
    float p  = 1.3333558e-3f;
    p = fmaf(f, p, 9.6181291e-3f);
    p = fmaf(f, p, 5.5504109e-2f);
    p = fmaf(f, p, 2.4022651e-1f);
    p = fmaf(f, p, 6.9314718e-1f);
    p = fmaf(f, p, 1.0f);
    return __int_as_float(__float_as_int(p) + (__float_as_int(z) << 23));
}

// ---- cp.async ------------------------------------------------------------
__device__ __forceinline__ unsigned saddr(const void* p) {
    return (unsigned)__cvta_generic_to_shared(p);
}
#define CPA16(d, s)  asm volatile("cp.async.cg.shared.global [%0],[%1],16;" :: "r"(d), "l"(s))
#define CPCOMMIT()   asm volatile("cp.async.commit_group;")
#define CPWAIT0()    asm volatile("cp.async.wait_group 0;" ::: "memory")

// SMEM: Ks[2][BN*DH] + Vs[2][BN*DH] + Ms[2][BN*MST]
#define SMEM_FLOATS (4 * BN * DH + 2 * BN * MST)

// Flash attention, fp32 exact. One query row per LANE PAIR (h = lane&1 owns
// D-half h). Changes vs prior round (issue was 27.7%: latency-bound):
//   * software exp -> removes ~1.9 ms chip-wide MUFU-pipe floor (268M expf)
//   * split-D halves q/acc regs; cp.async staging removes prefetch regs
//     -> <=128 regs -> 4 CTAs/SM -> 2x schedulable warps per SMSP
__global__ __launch_bounds__(NT, 4)
void fa_fp32_kernel(const float* __restrict__ Q,
                    const float* __restrict__ K,
                    const float* __restrict__ V,
                    const float* __restrict__ AM,
                    const unsigned int* __restrict__ PM,
                    float* __restrict__ O)
{
    extern __shared__ float smem[];
    float* Ks = smem;                    // [2][BN*DH]
    float* Vs = smem + 2 * BN * DH;      // [2][BN*DH]
    float* Ms = smem + 4 * BN * DH;      // [2][BN*MST] combined mask / scores

    const int tid   = threadIdx.x;
    const int lane  = tid & 31;
    const int w     = tid >> 5;
    const int h     = lane & 1;                 // D-half
    const int rloc  = (w << 4) + (lane >> 1);   // row within CTA, 0..63
    const int bh    = blockIdx.y;
    const int b     = bh >> 4;                  // H = 16
    const int qrow0 = blockIdx.x * BM;
    const int qrow  = qrow0 + rloc;
    const size_t base = (size_t)bh * SEQ * DH;

    // ---- q: my half-row (32 floats), pre-scaled by 1/8 ----
    ull q2[16];
    {
        const ulonglong2* qp = reinterpret_cast<const ulonglong2*>(
            Q + base + (size_t)qrow * DH + h * 32);
        const ull s2 = pack2(0.125f, 0.125f);
#pragma unroll
        for (int i = 0; i < 8; i++) {
            ulonglong2 qq = qp[i];
            q2[2 * i + 0] = mul2(qq.x, s2);
            q2[2 * i + 1] = mul2(qq.y, s2);
        }
    }
    ull acc2[16];
#pragma unroll
    for (int i = 0; i < 16; i++) acc2[i] = 0ull;

    float m = -1e30f, l = 0.f;

    // ---- tile staging helpers ----
    const float* Kbase = K + base;
    const float* Vbase = V + base;

    // K/V tile -> SMEM buffer via cp.async (4+4 x 16B per thread)
    auto stage_kv = [&](int t, int buf) {
        const float* kg = Kbase + (size_t)t * BN * DH;
        const float* vg = Vbase + (size_t)t * BN * DH;
        unsigned kd = saddr(Ks + buf * BN * DH);
        unsigned vd = saddr(Vs + buf * BN * DH);
#pragma unroll
        for (int i = 0; i < 4; i++) {
            int off = (i * NT + tid) * 4;          // float index
            CPA16(kd + off * 4, kg + off);
            CPA16(vd + off * 4, vg + off);
        }
    };
    // mask wave: 2 tasks/thread; raw loads kept in regs, combined at store
    auto mload = [&](int t, int i0, float4* a, uint4* p) {
        const int col0 = t * BN;
#pragma unroll
        for (int i = 0; i < 2; i++) {
            int tau = (i0 + i) * NT + tid;
            int row = tau >> 3, idx = tau & 7;
            a[i] = *reinterpret_cast<const float4*>(
                AM + (size_t)(qrow0 + row) * SEQ + col0 + idx * 4);
            p[i] = *reinterpret_cast<const uint4*>(
                PM + ((size_t)b * SEQ + (qrow0 + row)) * SEQ + col0 + idx * 4);
        }
    };
    auto mstore = [&](int buf, int i0, const float4* a, const uint4* p) {
        float* Mn = Ms + buf * BN * MST;
#pragma unroll
        for (int i = 0; i < 2; i++) {
            int tau = (i0 + i) * NT + tid;
            int row = tau >> 3, col = (tau & 7) * 4;
            Mn[(col + 0) * MST + row] = p[i].x ? -1e30f : a[i].x;
            Mn[(col + 1) * MST + row] = p[i].y ? -1e30f : a[i].y;
            Mn[(col + 2) * MST + row] = p[i].z ? -1e30f : a[i].z;
            Mn[(col + 3) * MST + row] = p[i].w ? -1e30f : a[i].w;
        }
    };

    // ---- prologue: tile 0 ----
    {
        stage_kv(0, 0); CPCOMMIT();
        float4 a[2]; uint4 p[2];
        mload(0, 0, a, p); mstore(0, 0, a, p);
        mload(0, 2, a, p); mstore(0, 2, a, p);
        CPWAIT0();
    }
    __syncthreads();

    int cur = 0;
    for (int t = 0; t < NTILES; t++) {
        const bool hn = (t + 1 < NTILES);
        float4 ma[2]; uint4 mp[2];
        if (hn) { stage_kv(t + 1, cur ^ 1); CPCOMMIT(); mload(t + 1, 0, ma, mp); }

        const float* Kc = Ks + cur * BN * DH;
        float*       Mc = Ms + cur * BN * MST;

        // ---- QK^T: half-dot per lane, shuffle-combine, mask, in-place ----
        float tm = -1e30f;
#pragma unroll 8
        for (int j = 0; j < BN; j++) {
            const float mk = Mc[j * MST + rloc];          // combined mask (read early)
            const ulonglong2* kr = reinterpret_cast<const ulonglong2*>(
                Kc + j * DH + h * 32);
            ull sa = 0ull, sb = 0ull, sc = 0ull, sd = 0ull;
#pragma unroll
            for (int dd = 0; dd < 4; dd++) {
                ulonglong2 k0 = kr[2 * dd + 0];
                ulonglong2 k1 = kr[2 * dd + 1];
                sa = fma2(q2[4 * dd + 0], k0.x, sa);
                sb = fma2(q2[4 * dd + 1], k0.y, sb);
                sc = fma2(q2[4 * dd + 2], k1.x, sc);
                sd = fma2(q2[4 * dd + 3], k1.y, sd);
            }
            ull s4 = add2(add2(sa, sb), add2(sc, sd));
            float lo, hi; unpack2(s4, lo, hi);
            float part = lo + hi;
            part += __shfl_xor_sync(0xffffffffu, part, 1); // both halves -> full dot
            float s = part + mk;
            tm = fmaxf(tm, s);
            if (h == 0) Mc[j * MST + rloc] = s;            // predicated store
        }
        __syncwarp();                                       // h=1 reads h=0's scores

        if (hn) { mstore(cur ^ 1, 0, ma, mp); mload(t + 1, 2, ma, mp); }

        // ---- online softmax update ----
        const float mnew = fmaxf(m, tm);
        const float corr = fexp(m - mnew);
        m = mnew;
        l *= corr;
        const ull cc = pack2(corr, corr);
#pragma unroll
        for (int i = 0; i < 16; i++) acc2[i] = mul2(acc2[i], cc);

        // ---- P @ V (half-row per lane) ----
        const float* Vc = Vs + cur * BN * DH;
#pragma unroll 8
        for (int j = 0; j < BN; j++) {
            const float p = fexp(Mc[j * MST + rloc] - mnew);
            l += p;
            const ull pp = pack2(p, p);
            const ulonglong2* vr = reinterpret_cast<const ulonglong2*>(
                Vc + j * DH + h * 32);
#pragma unroll
            for (int dd = 0; dd < 4; dd++) {
                ulonglong2 v0 = vr[2 * dd + 0];
                ulonglong2 v1 = vr[2 * dd + 1];
                acc2[4 * dd + 0] = fma2(pp, v0.x, acc2[4 * dd + 0]);
                acc2[4 * dd + 1] = fma2(pp, v0.y, acc2[4 * dd + 1]);
                acc2[4 * dd + 2] = fma2(pp, v1.x, acc2[4 * dd + 2]);
                acc2[4 * dd + 3] = fma2(pp, v1.y, acc2[4 * dd + 3]);
            }
        }

        if (hn) { mstore(cur ^ 1, 2, ma, mp); }
        CPWAIT0();
        __syncthreads();
        cur ^= 1;
    }

    // ---- epilogue ----
    const float inv = 1.f / l;
    const ull iv = pack2(inv, inv);
    ulonglong2* op = reinterpret_cast<ulonglong2*>(
        O + base + (size_t)qrow * DH + h * 32);
#pragma unroll
    for (int i = 0; i < 8; i++) {
        ulonglong2 o;
        o.x = mul2(acc2[2 * i + 0], iv);
        o.y = mul2(acc2[2 * i + 1], iv);
        op[i] = o;
    }
}

extern "C" void kernel_launch(void* const* d_in, const int* in_sizes, int n_in,
                              void* d_out, int out_size)
{
    // metadata order: q, k, v, att_mask, padding_mask (masks identified by size)
    const float* q = (const float*)d_in[0];
    const float* k = (const float*)d_in[1];
    const float* v = (const float*)d_in[2];

    const float*        am;
    const unsigned int* pm;
    if (in_sizes[3] == SEQ * SEQ) {
        am = (const float*)d_in[3];
        pm = (const unsigned int*)d_in[4];
    } else {
        am = (const float*)d_in[4];
        pm = (const unsigned int*)d_in[3];
    }
    float* out = (float*)d_out;

    const int smem_bytes = SMEM_FLOATS * (int)sizeof(float);   // 49408 B
    cudaFuncSetAttribute(fa_fp32_kernel,
                         cudaFuncAttributeMaxDynamicSharedMemorySize,
                         smem_bytes);

    dim3 grid(SEQ / BM, BATCH * HEADS);        // (32, 64)
    fa_fp32_kernel<<<grid, NT, smem_bytes>>>(q, k, v, am, pm, out);
}